// round 1
// baseline (speedup 1.0000x reference)
#include <cuda_runtime.h>
#include <cstdint>

// FeatureEmbeddingBank: 24 single-token embedding lookups + 8 multi-token
// (len 20) mean-pooled lookups. B=4096, EMB=64, VOCAB=100000 (+1 pad row 0).
//
// d_in[0] = int_feats  int32  [4096, 184]
// d_in[1] = W          fp32   [32, 100001, 64]
// d_out   =            fp32   [4096, 32, 64]

namespace {
constexpr int N_SINGLE  = 24;
constexpr int N_MULTI   = 8;
constexpr int MULTI_LEN = 20;
constexpr int N_FEAT    = N_SINGLE + N_MULTI;     // 32
constexpr int VOCAB     = 100000;
constexpr int EMB       = 64;
constexpr int TOTAL_W   = N_SINGLE + N_MULTI * MULTI_LEN;  // 184
constexpr int ROW_F4    = EMB / 4;                // 16 float4 per embedding row
constexpr int BATCH     = 4096;

constexpr int GROUPS_PER_BLOCK = 16;              // 16 lanes per group, 256 thr/block
constexpr int THREADS = GROUPS_PER_BLOCK * 16;
}

// ---------------------------------------------------------------------------
// Kernel A: single-token features. One 16-lane group per (b, f) pair.
// Each lane loads one float4 (16 B) -> group gathers one 256 B embedding row.
// Uniform work: exactly 1 gather + 1 store per group.
// ---------------------------------------------------------------------------
__global__ __launch_bounds__(THREADS)
void feb_single(const int* __restrict__ idx,
                const float4* __restrict__ W,
                float4* __restrict__ out)
{
    const int gid  = blockIdx.x * GROUPS_PER_BLOCK + (threadIdx.x >> 4);
    const int lane = threadIdx.x & 15;

    const int b = gid / N_SINGLE;          // grid sized exactly; no bounds check
    const int f = gid - b * N_SINGLE;

    int v = __ldg(idx + (size_t)b * TOTAL_W + f);
    v = min(max(v, 0), VOCAB);

    const float4 e = __ldg(W + ((size_t)f * (VOCAB + 1) + (size_t)v) * ROW_F4 + lane);
    out[((size_t)b * N_FEAT + f) * ROW_F4 + lane] = e;
}

// ---------------------------------------------------------------------------
// Kernel B: multi-token features. One 16-lane group per (b, m) pair.
// 20 fully-unrolled independent gathers per thread -> MLP ~ 20, hides DRAM
// latency. Mean over count of nonzero tokens (min 1).
// ---------------------------------------------------------------------------
__global__ __launch_bounds__(THREADS)
void feb_multi(const int* __restrict__ idx,
               const float4* __restrict__ W,
               float4* __restrict__ out)
{
    const int gid  = blockIdx.x * GROUPS_PER_BLOCK + (threadIdx.x >> 4);
    const int lane = threadIdx.x & 15;

    const int b = gid >> 3;                // N_MULTI = 8
    const int m = gid & 7;
    const int f = N_SINGLE + m;

    const int* __restrict__ p =
        idx + (size_t)b * TOTAL_W + N_SINGLE + m * MULTI_LEN;
    const float4* __restrict__ Wf =
        W + (size_t)f * (VOCAB + 1) * ROW_F4 + lane;

    float ax = 0.f, ay = 0.f, az = 0.f, aw = 0.f;
    int cnt = 0;

#pragma unroll
    for (int t = 0; t < MULTI_LEN; ++t) {
        int v = __ldg(p + t);
        v = min(max(v, 0), VOCAB);
        cnt += (v != 0);
        const float4 e = __ldg(Wf + (size_t)v * ROW_F4);
        ax += e.x; ay += e.y; az += e.z; aw += e.w;
    }

    const float inv = 1.0f / (float)max(cnt, 1);
    out[((size_t)b * N_FEAT + f) * ROW_F4 + lane] =
        make_float4(ax * inv, ay * inv, az * inv, aw * inv);
}

// ---------------------------------------------------------------------------
extern "C" void kernel_launch(void* const* d_in, const int* in_sizes, int n_in,
                              void* d_out, int out_size)
{
    const int*    idx = (const int*)d_in[0];
    const float4* W   = (const float4*)d_in[1];
    float4*       out = (float4*)d_out;

    (void)in_sizes; (void)n_in; (void)out_size;

    // Singles: 4096 * 24 groups = 98304 groups -> 6144 blocks of 16 groups.
    {
        const int n_groups = BATCH * N_SINGLE;
        feb_single<<<n_groups / GROUPS_PER_BLOCK, THREADS>>>(idx, W, out);
    }
    // Multi: 4096 * 8 groups = 32768 groups -> 2048 blocks of 16 groups.
    {
        const int n_groups = BATCH * N_MULTI;
        feb_multi<<<n_groups / GROUPS_PER_BLOCK, THREADS>>>(idx, W, out);
    }
}

// round 4
// speedup vs baseline: 1.1249x; 1.1249x over previous
#include <cuda_runtime.h>
#include <cstdint>

// FeatureEmbeddingBank: 24 single-token embedding lookups + 8 multi-token
// (len 20) mean-pooled lookups. B=4096, EMB=64, VOCAB=100000 (+1 pad row 0).
//
// d_in[0] = int_feats  int32  [4096, 184]
// d_in[1] = W          fp32   [32, 100001, 64]
// d_out   =            fp32   [4096, 32, 64]
//
// Two-kernel structure (known-good from R1). R3 change: feb_multi splits the
// 20 tokens across warp halves (10-deep independent LDG.128 chain per thread
// instead of 20-deep) so the chain pipelines within the register budget,
// then combines with shfl_xor(16).

namespace {
constexpr int N_SINGLE  = 24;
constexpr int N_MULTI   = 8;
constexpr int MULTI_LEN = 20;
constexpr int HALF_LEN  = MULTI_LEN / 2;          // 10
constexpr int N_FEAT    = N_SINGLE + N_MULTI;     // 32
constexpr int VOCAB     = 100000;
constexpr int EMB       = 64;
constexpr int TOTAL_W   = N_SINGLE + N_MULTI * MULTI_LEN;  // 184
constexpr int ROW_F4    = EMB / 4;                // 16 float4 per embedding row
constexpr int BATCH     = 4096;

constexpr int GROUPS_PER_BLOCK = 16;              // single kernel: 16 lanes/group
constexpr int THREADS = 256;                      // 8 warps per block
}

// ---------------------------------------------------------------------------
// Kernel A: single-token features. One 16-lane group per (b, f) pair.
// Each lane loads one float4 (16 B) -> group gathers one 256 B embedding row.
// (Identical to the R1 version that passed.)
// ---------------------------------------------------------------------------
__global__ __launch_bounds__(THREADS)
void feb_single(const int* __restrict__ idx,
                const float4* __restrict__ W,
                float4* __restrict__ out)
{
    const int gid  = blockIdx.x * GROUPS_PER_BLOCK + (threadIdx.x >> 4);
    const int lane = threadIdx.x & 15;

    const int b = gid / N_SINGLE;          // grid sized exactly; no bounds check
    const int f = gid - b * N_SINGLE;

    int v = __ldg(idx + (size_t)b * TOTAL_W + f);
    v = min(max(v, 0), VOCAB);

    const float4 e = __ldg(W + ((size_t)f * (VOCAB + 1) + (size_t)v) * ROW_F4 + lane);
    out[((size_t)b * N_FEAT + f) * ROW_F4 + lane] = e;
}

// ---------------------------------------------------------------------------
// Kernel B: multi-token features. One full warp per (b, m) pair.
// Lanes 0-15 gather tokens 0-9, lanes 16-31 gather tokens 10-19; each lane
// owns one float4 slot of the 256 B row. 10 independent gathers per thread
// (fits the register budget -> high MLP), then shfl_xor(16) combine and
// lanes 0-15 store the mean.
// ---------------------------------------------------------------------------
__global__ __launch_bounds__(THREADS)
void feb_multi(const int* __restrict__ idx,
               const float4* __restrict__ W,
               float4* __restrict__ out)
{
    const int wid  = blockIdx.x * (THREADS / 32) + (threadIdx.x >> 5);
    const int lane = threadIdx.x & 31;

    const int b = wid >> 3;                // N_MULTI = 8
    const int m = wid & 7;
    const int f = N_SINGLE + m;

    const int half = lane >> 4;            // 0: tokens 0-9, 1: tokens 10-19
    const int sub  = lane & 15;            // float4 slot within the row

    const int* __restrict__ p =
        idx + (size_t)b * TOTAL_W + N_SINGLE + m * MULTI_LEN + half * HALF_LEN;
    const float4* __restrict__ Wf =
        W + (size_t)f * (VOCAB + 1) * ROW_F4 + sub;

    float ax = 0.f, ay = 0.f, az = 0.f, aw = 0.f;
    int cnt = 0;

#pragma unroll
    for (int t = 0; t < HALF_LEN; ++t) {
        int v = __ldg(p + t);
        v = min(max(v, 0), VOCAB);
        cnt += (v != 0);
        const float4 e = __ldg(Wf + (size_t)v * ROW_F4);
        ax += e.x; ay += e.y; az += e.z; aw += e.w;
    }

    // combine the two token-halves across the warp
    ax  += __shfl_xor_sync(0xffffffffu, ax, 16);
    ay  += __shfl_xor_sync(0xffffffffu, ay, 16);
    az  += __shfl_xor_sync(0xffffffffu, az, 16);
    aw  += __shfl_xor_sync(0xffffffffu, aw, 16);
    cnt += __shfl_xor_sync(0xffffffffu, cnt, 16);

    if (half == 0) {
        const float inv = 1.0f / (float)max(cnt, 1);
        out[((size_t)b * N_FEAT + f) * ROW_F4 + sub] =
            make_float4(ax * inv, ay * inv, az * inv, aw * inv);
    }
}

// ---------------------------------------------------------------------------
extern "C" void kernel_launch(void* const* d_in, const int* in_sizes, int n_in,
                              void* d_out, int out_size)
{
    const int*    idx = (const int*)d_in[0];
    const float4* W   = (const float4*)d_in[1];
    float4*       out = (float4*)d_out;

    (void)in_sizes; (void)n_in; (void)out_size;

    // Singles first (short blocks), multi second (longer warps dominate).
    {
        const int n_groups = BATCH * N_SINGLE;             // 98304
        feb_single<<<n_groups / GROUPS_PER_BLOCK, THREADS>>>(idx, W, out);
    }
    {
        const int n_warp_pairs = BATCH * N_MULTI;          // 32768 warps
        feb_multi<<<n_warp_pairs / (THREADS / 32), THREADS>>>(idx, W, out);
    }
}

// round 5
// speedup vs baseline: 1.2989x; 1.1547x over previous
#include <cuda_runtime.h>
#include <cstdint>

// FeatureEmbeddingBank: 24 single-token lookups + 8 multi-token (len 20)
// mean-pooled lookups. B=4096, EMB=64, VOCAB=100000 (+1 pad row 0).
//
// d_in[0] = int_feats  int32  [4096, 184]
// d_in[1] = W          fp32   [32, 100001, 64]
// d_out   =            fp32   [4096, 32, 64]
//
// Fused single-kernel design (one launch):
//   blocks [0, NB_MULTI):   multi features, 1 warp per (b, m) pair.
//     Lanes 0-15 gather tokens 0-9, lanes 16-31 gather tokens 10-19; each
//     lane owns one float4 of the 256 B row -> 10-deep independent LDG.128
//     chain per thread, shfl_xor(16) combine, lanes 0-15 store the mean.
//     (This layout measured 25.1 us standalone in R4.)
//   blocks [NB_MULTI, ..):  single features, each thread serves the same
//     float4 slot of TWO (b, f) pairs -> 2 independent gathers per thread.
//   Multi blocks first: long blocks start early, short singles fill the tail.

namespace {
constexpr int N_SINGLE  = 24;
constexpr int N_MULTI   = 8;
constexpr int MULTI_LEN = 20;
constexpr int HALF_LEN  = MULTI_LEN / 2;           // 10
constexpr int N_FEAT    = N_SINGLE + N_MULTI;      // 32
constexpr int VOCAB     = 100000;
constexpr int EMB       = 64;
constexpr int TOTAL_W   = N_SINGLE + N_MULTI * MULTI_LEN;  // 184
constexpr int ROW_F4    = EMB / 4;                 // 16 float4 per row
constexpr int BATCH     = 4096;

constexpr int THREADS   = 256;                     // 8 warps

// multi: 1 warp per (b,m) pair -> 4096*8 / 8 warps = 4096 blocks
constexpr int NB_MULTI  = BATCH * N_MULTI / (THREADS / 32);     // 4096
// single: 32 pairs per block (16 groups x 2 pairs per thread)
constexpr int PAIRS_PER_BLOCK = 2 * (THREADS / 16);             // 32
constexpr int NB_SINGLE = BATCH * N_SINGLE / PAIRS_PER_BLOCK;   // 3072
constexpr int NB_TOTAL  = NB_MULTI + NB_SINGLE;                 // 7168
}

__global__ __launch_bounds__(THREADS)
void feb_fused(const int* __restrict__ idx,
               const float4* __restrict__ W,
               float4* __restrict__ out)
{
    const int bid = blockIdx.x;

    if (bid < NB_MULTI) {
        // ---------------- multi-token path: one warp per (b, m) ----------------
        const int wid  = bid * (THREADS / 32) + (threadIdx.x >> 5);
        const int lane = threadIdx.x & 31;

        const int b = wid >> 3;                  // N_MULTI = 8
        const int m = wid & 7;
        const int f = N_SINGLE + m;

        const int half = lane >> 4;              // 0: tokens 0-9, 1: tokens 10-19
        const int sub  = lane & 15;              // float4 slot within the row

        const int* __restrict__ p =
            idx + (size_t)b * TOTAL_W + N_SINGLE + m * MULTI_LEN + half * HALF_LEN;
        const float4* __restrict__ Wf =
            W + (size_t)f * (VOCAB + 1) * ROW_F4 + sub;

        float ax = 0.f, ay = 0.f, az = 0.f, aw = 0.f;
        int cnt = 0;

#pragma unroll
        for (int t = 0; t < HALF_LEN; ++t) {
            int v = __ldg(p + t);
            v = min(max(v, 0), VOCAB);
            cnt += (v != 0);
            const float4 e = __ldg(Wf + (size_t)v * ROW_F4);
            ax += e.x; ay += e.y; az += e.z; aw += e.w;
        }

        // combine the two token-halves across the warp
        ax  += __shfl_xor_sync(0xffffffffu, ax, 16);
        ay  += __shfl_xor_sync(0xffffffffu, ay, 16);
        az  += __shfl_xor_sync(0xffffffffu, az, 16);
        aw  += __shfl_xor_sync(0xffffffffu, aw, 16);
        cnt += __shfl_xor_sync(0xffffffffu, cnt, 16);

        if (half == 0) {
            const float inv = 1.0f / (float)max(cnt, 1);
            out[((size_t)b * N_FEAT + f) * ROW_F4 + sub] =
                make_float4(ax * inv, ay * inv, az * inv, aw * inv);
        }
    } else {
        // -------- single-token path: 2 independent (b, f) pairs per thread -----
        const int group = threadIdx.x >> 4;      // 0..15
        const int lane  = threadIdx.x & 15;      // float4 slot

        const int pair0 = (bid - NB_MULTI) * PAIRS_PER_BLOCK + group;
        const int pair1 = pair0 + (THREADS / 16);    // +16

        const int b0 = pair0 / N_SINGLE, f0 = pair0 - b0 * N_SINGLE;
        const int b1 = pair1 / N_SINGLE, f1 = pair1 - b1 * N_SINGLE;

        int v0 = __ldg(idx + (size_t)b0 * TOTAL_W + f0);
        int v1 = __ldg(idx + (size_t)b1 * TOTAL_W + f1);
        v0 = min(max(v0, 0), VOCAB);
        v1 = min(max(v1, 0), VOCAB);

        const float4 e0 =
            __ldg(W + ((size_t)f0 * (VOCAB + 1) + (size_t)v0) * ROW_F4 + lane);
        const float4 e1 =
            __ldg(W + ((size_t)f1 * (VOCAB + 1) + (size_t)v1) * ROW_F4 + lane);

        out[((size_t)b0 * N_FEAT + f0) * ROW_F4 + lane] = e0;
        out[((size_t)b1 * N_FEAT + f1) * ROW_F4 + lane] = e1;
    }
}

// ---------------------------------------------------------------------------
extern "C" void kernel_launch(void* const* d_in, const int* in_sizes, int n_in,
                              void* d_out, int out_size)
{
    const int*    idx = (const int*)d_in[0];
    const float4* W   = (const float4*)d_in[1];
    float4*       out = (float4*)d_out;

    (void)in_sizes; (void)n_in; (void)out_size;

    feb_fused<<<NB_TOTAL, THREADS>>>(idx, W, out);
}